// round 1
// baseline (speedup 1.0000x reference)
#include <cuda_runtime.h>
#include <math.h>

// ---------------- problem constants ----------------
#define NIMG 4
#define BATCH 8
#define SEQ 576
#define DIM 256
#define NHEAD 8
#define DHEAD 32
#define NLAYER 6
#define MLPDIM 512
#define NB (NIMG*BATCH)      // 32
#define TOK (NB*SEQ)         // 18432
#define KPATCH 768           // 3*16*16
#define GRID24 24

// ---------------- scratch (device globals; no allocation allowed) ----------------
__device__ float g_im2col[(long)NIMG*BATCH*SEQ*KPATCH];  // 56.6 MB
__device__ float g_pe[(long)TOK*DIM];                    // 18.9 MB
__device__ float g_qkv[(long)TOK*3*DIM];                 // 56.6 MB
__device__ float g_o[(long)TOK*DIM];                     // 18.9 MB
__device__ float g_feat[BATCH*NIMG*DIM];

// ---------------- im2col ----------------
__global__ void im2col_k(const float* __restrict__ x) {
    long idx = (long)blockIdx.x*256 + threadIdx.x;
    const long total = (long)NIMG*BATCH*SEQ*KPATCH;
    if (idx >= total) return;
    int k   = (int)(idx % KPATCH);
    long r  = idx / KPATCH;
    int s   = (int)(r % SEQ);
    int b   = (int)((r / SEQ) % BATCH);
    int ni  = (int)(r / ((long)SEQ*BATCH));
    int c   = k >> 8;
    int py  = (k >> 4) & 15;
    int px  = k & 15;
    int gy  = s / GRID24, gx = s % GRID24;
    g_im2col[idx] = x[(((long)b*12 + ni*3 + c)*384 + gy*16 + py)*384 + gx*16 + px];
}

// ---------------- generic SGEMM: C[M,N] = A[M,K] @ Bw[N,K]^T (+bias)(+pos_enc) ----------------
// 64x64 tile, BK=16, 256 threads, 4x4 microtile. M%64==0, N%64==0, K%16==0 guaranteed.
__global__ __launch_bounds__(256) void sgemm64(
    const float* __restrict__ A, const float* __restrict__ Bw, float* __restrict__ C,
    int M, int N, int K,
    const float* __restrict__ bias, const float* __restrict__ pos,
    long strideA, long strideB, long strideC, int strideBias)
{
    A  += (long)blockIdx.z * strideA;
    Bw += (long)blockIdx.z * strideB;
    C  += (long)blockIdx.z * strideC;
    if (bias) bias += (long)blockIdx.z * strideBias;

    __shared__ float As[16][68];
    __shared__ float Bs[16][68];

    int tid  = threadIdx.x;
    int m0   = blockIdx.y * 64;
    int n0   = blockIdx.x * 64;
    int arow = tid >> 2;
    int ac4  = (tid & 3) * 4;
    int tm   = tid >> 4;
    int tn   = tid & 15;

    float acc[4][4] = {};

    for (int k0 = 0; k0 < K; k0 += 16) {
        float4 av = *(const float4*)&A[(long)(m0 + arow)*K + k0 + ac4];
        float4 bv = *(const float4*)&Bw[(long)(n0 + arow)*K + k0 + ac4];
        As[ac4+0][arow] = av.x; As[ac4+1][arow] = av.y;
        As[ac4+2][arow] = av.z; As[ac4+3][arow] = av.w;
        Bs[ac4+0][arow] = bv.x; Bs[ac4+1][arow] = bv.y;
        Bs[ac4+2][arow] = bv.z; Bs[ac4+3][arow] = bv.w;
        __syncthreads();
        #pragma unroll
        for (int kk = 0; kk < 16; kk++) {
            float4 a = *(const float4*)&As[kk][tm*4];
            float4 b = *(const float4*)&Bs[kk][tn*4];
            acc[0][0] += a.x*b.x; acc[0][1] += a.x*b.y; acc[0][2] += a.x*b.z; acc[0][3] += a.x*b.w;
            acc[1][0] += a.y*b.x; acc[1][1] += a.y*b.y; acc[1][2] += a.y*b.z; acc[1][3] += a.y*b.w;
            acc[2][0] += a.z*b.x; acc[2][1] += a.z*b.y; acc[2][2] += a.z*b.z; acc[2][3] += a.z*b.w;
            acc[3][0] += a.w*b.x; acc[3][1] += a.w*b.y; acc[3][2] += a.w*b.z; acc[3][3] += a.w*b.w;
        }
        __syncthreads();
    }

    int n = n0 + tn*4;
    float4 bb = {0.f,0.f,0.f,0.f};
    if (bias) { bb.x = bias[n]; bb.y = bias[n+1]; bb.z = bias[n+2]; bb.w = bias[n+3]; }
    #pragma unroll
    for (int ii = 0; ii < 4; ii++) {
        int m = m0 + tm*4 + ii;
        float4 v;
        v.x = acc[ii][0] + bb.x; v.y = acc[ii][1] + bb.y;
        v.z = acc[ii][2] + bb.z; v.w = acc[ii][3] + bb.w;
        if (pos) {
            const float* pr = pos + (long)(m % SEQ)*DIM + n;   // only used when N==DIM
            v.x += pr[0]; v.y += pr[1]; v.z += pr[2]; v.w += pr[3];
        }
        *(float4*)&C[(long)m*N + n] = v;
    }
}

// ---------------- fused attention ----------------
// One CTA per (nb, 32-query tile). Loops heads; K/V tile + scores + head-mean in SMEM.
#define KSTR 36
#define SSTR 577
#define ATTN_SMEM ((SEQ*KSTR + 2*32*SSTR)*4)   // 230,656 B

__global__ __launch_bounds__(256, 1) void attn_k(
    const float* __restrict__ qkv, float* __restrict__ o,
    float* __restrict__ attn_out, int layer)
{
    extern __shared__ float sm[];
    float* Ks = sm;                    // [576][36]   K, then reused for V
    float* Ss = sm + SEQ*KSTR;         // [32][577]   scores -> probs
    float* Am = Ss + 32*SSTR;          // [32][577]   head-mean accumulator

    int tid = threadIdx.x;
    int qt  = blockIdx.x;              // 0..17
    int nb  = blockIdx.y;              // 0..31
    const float* qbase = qkv + (long)nb*SEQ*768;

    for (int t = tid; t < 32*SSTR; t += 256) Am[t] = 0.f;

    int q = tid & 31;
    int i = tid >> 5;
    int qrow = qt*32 + q;

    for (int h = 0; h < NHEAD; h++) {
        __syncthreads();   // Ks free (prev PV done), Ss free
        // load K_h tile [576,32]
        for (int t = tid; t < SEQ*8; t += 256) {
            int kr = t >> 3, c4 = (t & 7)*4;
            *(float4*)&Ks[kr*KSTR + c4] =
                *(const float4*)&qbase[(long)kr*768 + 256 + h*32 + c4];
        }
        // q fragment in registers (scaled)
        float qf[32];
        {
            const float* qp = &qbase[(long)qrow*768 + h*32];
            #pragma unroll
            for (int u = 0; u < 8; u++) {
                float4 v = *(const float4*)&qp[u*4];
                qf[u*4+0] = v.x * 0.17677669529663687f;
                qf[u*4+1] = v.y * 0.17677669529663687f;
                qf[u*4+2] = v.z * 0.17677669529663687f;
                qf[u*4+3] = v.w * 0.17677669529663687f;
            }
        }
        __syncthreads();
        // scores: warp reads one broadcast K row, 32 q's per warp-instant
        for (int kb = i; kb < SEQ; kb += 8) {
            const float4* krow = (const float4*)&Ks[kb*KSTR];
            float a = 0.f;
            #pragma unroll
            for (int u = 0; u < 8; u++) {
                float4 kv = krow[u];
                a += qf[u*4+0]*kv.x + qf[u*4+1]*kv.y + qf[u*4+2]*kv.z + qf[u*4+3]*kv.w;
            }
            Ss[q*SSTR + kb] = a;
        }
        __syncthreads();
        // softmax per q-row (8 lanes per row), accumulate head mean
        {
            int w = tid >> 5, lane = tid & 31;
            int sq = w*4 + (lane >> 3);
            int kk0 = lane & 7;
            float mx = -1e30f;
            for (int k = kk0; k < SEQ; k += 8) mx = fmaxf(mx, Ss[sq*SSTR + k]);
            mx = fmaxf(mx, __shfl_xor_sync(0xffffffffu, mx, 1));
            mx = fmaxf(mx, __shfl_xor_sync(0xffffffffu, mx, 2));
            mx = fmaxf(mx, __shfl_xor_sync(0xffffffffu, mx, 4));
            float sum = 0.f;
            for (int k = kk0; k < SEQ; k += 8) {
                float e = __expf(Ss[sq*SSTR + k] - mx);
                Ss[sq*SSTR + k] = e;
                sum += e;
            }
            sum += __shfl_xor_sync(0xffffffffu, sum, 1);
            sum += __shfl_xor_sync(0xffffffffu, sum, 2);
            sum += __shfl_xor_sync(0xffffffffu, sum, 4);
            float rinv = __frcp_rn(sum);
            for (int k = kk0; k < SEQ; k += 8) {
                float p = Ss[sq*SSTR + k] * rinv;
                Ss[sq*SSTR + k] = p;
                Am[sq*SSTR + k] += p * 0.125f;
            }
        }
        // load V_h into Ks (K no longer needed)
        for (int t = tid; t < SEQ*8; t += 256) {
            int kr = t >> 3, c4 = (t & 7)*4;
            *(float4*)&Ks[kr*KSTR + c4] =
                *(const float4*)&qbase[(long)kr*768 + 512 + h*32 + c4];
        }
        __syncthreads();
        // PV: warp owns 4 head-dims (broadcast V row), 32 q's across lanes
        {
            int dh4 = (tid >> 5)*4;
            int pq  = tid & 31;
            const float* srow = &Ss[pq*SSTR];
            float4 accv = {0.f,0.f,0.f,0.f};
            #pragma unroll 8
            for (int k = 0; k < SEQ; k++) {
                float p = srow[k];
                float4 v = *(const float4*)&Ks[k*KSTR + dh4];
                accv.x += p*v.x; accv.y += p*v.y; accv.z += p*v.z; accv.w += p*v.w;
            }
            *(float4*)&o[((long)nb*SEQ + qt*32 + pq)*DIM + h*32 + dh4] = accv;
        }
    }
    __syncthreads();
    // write head-mean attention straight into d_out
    float* aout = attn_out + (long)(layer*NB + nb)*SEQ*SEQ + (long)qt*32*SEQ;
    for (int t = tid; t < 32*SEQ; t += 256) {
        int aq = t / SEQ, ak = t % SEQ;
        aout[(long)aq*SEQ + ak] = Am[aq*SSTR + ak];
    }
}

// ---------------- feature mean over sequence ----------------
__global__ void feat_k(void) {
    int ni = blockIdx.x, b = blockIdx.y, d = threadIdx.x;  // 256 threads
    const float* p = g_pe + ((long)(ni*BATCH + b)*SEQ)*DIM + d;
    float s = 0.f;
    for (int t = 0; t < SEQ; t++) s += p[(long)t*DIM];
    g_feat[b*(NIMG*DIM) + ni*DIM + d] = s * (1.0f/576.0f);
}

// ---------------- MLP head ----------------
__global__ void head_k(const float* __restrict__ w1, const float* __restrict__ b1,
                       const float* __restrict__ w2, const float* __restrict__ b2,
                       float* __restrict__ out) {
    __shared__ float fs[NIMG*DIM];
    __shared__ float hs[MLPDIM];
    int b = blockIdx.x, tid = threadIdx.x;   // 512 threads
    for (int t = tid; t < NIMG*DIM; t += MLPDIM) fs[t] = g_feat[b*NIMG*DIM + t];
    __syncthreads();
    float a = b1[tid];
    const float* wr = w1 + (long)tid*(NIMG*DIM);
    for (int d2 = 0; d2 < NIMG*DIM; d2++) a += fs[d2]*wr[d2];
    hs[tid] = fmaxf(a, 0.f) * w2[tid];
    __syncthreads();
    for (int st = 256; st > 0; st >>= 1) {
        if (tid < st) hs[tid] += hs[tid + st];
        __syncthreads();
    }
    if (tid == 0) out[b] = hs[0] + b2[0];
}

// ---------------- launch ----------------
extern "C" void kernel_launch(void* const* d_in, const int* in_sizes, int n_in,
                              void* d_out, int out_size) {
    const float* x      = (const float*)d_in[0];
    const float* conv_w = (const float*)d_in[1];
    const float* conv_b = (const float*)d_in[2];
    const float* pos_e  = (const float*)d_in[3];
    const float* in_w   = (const float*)d_in[4];
    const float* in_b   = (const float*)d_in[5];
    const float* out_w  = (const float*)d_in[6];
    const float* out_b  = (const float*)d_in[7];
    const float* hw1    = (const float*)d_in[8];
    const float* hb1    = (const float*)d_in[9];
    const float* hw2    = (const float*)d_in[10];
    const float* hb2    = (const float*)d_in[11];

    float* out  = (float*)d_out;            // [8]
    float* attn = out + BATCH;              // [6,4,8,576,576]

    cudaFuncSetAttribute(attn_k, cudaFuncAttributeMaxDynamicSharedMemorySize, ATTN_SMEM);

    float *im2col_p, *pe_p, *qkv_p, *o_p;
    cudaGetSymbolAddress((void**)&im2col_p, g_im2col);
    cudaGetSymbolAddress((void**)&pe_p,     g_pe);
    cudaGetSymbolAddress((void**)&qkv_p,    g_qkv);
    cudaGetSymbolAddress((void**)&o_p,      g_o);

    // 1) im2col
    {
        long total = (long)NIMG*BATCH*SEQ*KPATCH;
        im2col_k<<<(int)((total + 255)/256), 256>>>(x);
    }
    // 2) patch-embed GEMM per image (grid.z = NI), + conv_b + pos_enc
    {
        dim3 g(DIM/64, (BATCH*SEQ)/64, NIMG);
        sgemm64<<<g, 256>>>(im2col_p, conv_w, pe_p,
                            BATCH*SEQ, DIM, KPATCH,
                            conv_b, pos_e,
                            (long)BATCH*SEQ*KPATCH, (long)DIM*KPATCH,
                            (long)BATCH*SEQ*DIM, DIM);
    }
    // 3) transformer layers
    for (int l = 0; l < NLAYER; l++) {
        {
            dim3 g((3*DIM)/64, TOK/64, 1);
            sgemm64<<<g, 256>>>(pe_p, in_w + (long)l*3*DIM*DIM, qkv_p,
                                TOK, 3*DIM, DIM,
                                in_b + (long)l*3*DIM, nullptr, 0, 0, 0, 0);
        }
        {
            dim3 g(SEQ/32, NB, 1);
            attn_k<<<g, 256, ATTN_SMEM>>>(qkv_p, o_p, attn, l);
        }
        {
            dim3 g(DIM/64, TOK/64, 1);
            sgemm64<<<g, 256>>>(o_p, out_w + (long)l*DIM*DIM, pe_p,
                                TOK, DIM, DIM,
                                out_b + (long)l*DIM, nullptr, 0, 0, 0, 0);
        }
    }
    // 4) sequence-mean features + MLP head
    {
        dim3 g(NIMG, BATCH);
        feat_k<<<g, DIM>>>();
    }
    head_k<<<BATCH, MLPDIM>>>(hw1, hb1, hw2, hb2, out);
}

// round 2
// speedup vs baseline: 1.5893x; 1.5893x over previous
#include <cuda_runtime.h>
#include <math.h>

// ---------------- problem constants ----------------
#define NIMG 4
#define BATCH 8
#define SEQ 576
#define DIM 256
#define NHEAD 8
#define DHEAD 32
#define NLAYER 6
#define MLPDIM 512
#define NB (NIMG*BATCH)      // 32
#define TOK (NB*SEQ)         // 18432
#define KPATCH 768           // 3*16*16
#define GRID24 24

// ---------------- scratch (device globals; no allocation allowed) ----------------
__device__ float g_im2col[(long)NIMG*BATCH*SEQ*KPATCH];  // 56.6 MB
__device__ float g_pe[(long)TOK*DIM];                    // 18.9 MB
__device__ float g_qkv[(long)TOK*3*DIM];                 // 56.6 MB
__device__ float g_o[(long)TOK*DIM];                     // 18.9 MB
__device__ float g_feat[BATCH*NIMG*DIM];

// ---------------- im2col ----------------
__global__ void im2col_k(const float* __restrict__ x) {
    long idx = (long)blockIdx.x*256 + threadIdx.x;
    const long total = (long)NIMG*BATCH*SEQ*KPATCH;
    if (idx >= total) return;
    int k   = (int)(idx % KPATCH);
    long r  = idx / KPATCH;
    int s   = (int)(r % SEQ);
    int b   = (int)((r / SEQ) % BATCH);
    int ni  = (int)(r / ((long)SEQ*BATCH));
    int c   = k >> 8;
    int py  = (k >> 4) & 15;
    int px  = k & 15;
    int gy  = s / GRID24, gx = s % GRID24;
    g_im2col[idx] = x[(((long)b*12 + ni*3 + c)*384 + gy*16 + py)*384 + gx*16 + px];
}

// ---------------- generic SGEMM: C[M,N] = A[M,K] @ Bw[N,K]^T (+bias)(+pos_enc) ----------------
__global__ __launch_bounds__(256) void sgemm64(
    const float* __restrict__ A, const float* __restrict__ Bw, float* __restrict__ C,
    int M, int N, int K,
    const float* __restrict__ bias, const float* __restrict__ pos,
    long strideA, long strideB, long strideC, int strideBias)
{
    A  += (long)blockIdx.z * strideA;
    Bw += (long)blockIdx.z * strideB;
    C  += (long)blockIdx.z * strideC;
    if (bias) bias += (long)blockIdx.z * strideBias;

    __shared__ float As[16][68];
    __shared__ float Bs[16][68];

    int tid  = threadIdx.x;
    int m0   = blockIdx.y * 64;
    int n0   = blockIdx.x * 64;
    int arow = tid >> 2;
    int ac4  = (tid & 3) * 4;
    int tm   = tid >> 4;
    int tn   = tid & 15;

    float acc[4][4] = {};

    for (int k0 = 0; k0 < K; k0 += 16) {
        float4 av = *(const float4*)&A[(long)(m0 + arow)*K + k0 + ac4];
        float4 bv = *(const float4*)&Bw[(long)(n0 + arow)*K + k0 + ac4];
        As[ac4+0][arow] = av.x; As[ac4+1][arow] = av.y;
        As[ac4+2][arow] = av.z; As[ac4+3][arow] = av.w;
        Bs[ac4+0][arow] = bv.x; Bs[ac4+1][arow] = bv.y;
        Bs[ac4+2][arow] = bv.z; Bs[ac4+3][arow] = bv.w;
        __syncthreads();
        #pragma unroll
        for (int kk = 0; kk < 16; kk++) {
            float4 a = *(const float4*)&As[kk][tm*4];
            float4 b = *(const float4*)&Bs[kk][tn*4];
            acc[0][0] += a.x*b.x; acc[0][1] += a.x*b.y; acc[0][2] += a.x*b.z; acc[0][3] += a.x*b.w;
            acc[1][0] += a.y*b.x; acc[1][1] += a.y*b.y; acc[1][2] += a.y*b.z; acc[1][3] += a.y*b.w;
            acc[2][0] += a.z*b.x; acc[2][1] += a.z*b.y; acc[2][2] += a.z*b.z; acc[2][3] += a.z*b.w;
            acc[3][0] += a.w*b.x; acc[3][1] += a.w*b.y; acc[3][2] += a.w*b.z; acc[3][3] += a.w*b.w;
        }
        __syncthreads();
    }

    int n = n0 + tn*4;
    float4 bb = {0.f,0.f,0.f,0.f};
    if (bias) { bb.x = bias[n]; bb.y = bias[n+1]; bb.z = bias[n+2]; bb.w = bias[n+3]; }
    #pragma unroll
    for (int ii = 0; ii < 4; ii++) {
        int m = m0 + tm*4 + ii;
        float4 v;
        v.x = acc[ii][0] + bb.x; v.y = acc[ii][1] + bb.y;
        v.z = acc[ii][2] + bb.z; v.w = acc[ii][3] + bb.w;
        if (pos) {
            const float* pr = pos + (long)(m % SEQ)*DIM + n;
            v.x += pr[0]; v.y += pr[1]; v.z += pr[2]; v.w += pr[3];
        }
        *(float4*)&C[(long)m*N + n] = v;
    }
}

// ---------------- tf32 mma helpers ----------------
__device__ __forceinline__ unsigned f2tf(float f) {
    unsigned u; asm("cvt.rna.tf32.f32 %0, %1;" : "=r"(u) : "f"(f)); return u;
}
__device__ __forceinline__ void mma_tf32(float* d, const unsigned* a, unsigned b0, unsigned b1) {
    asm volatile(
        "mma.sync.aligned.m16n8k8.row.col.f32.tf32.tf32.f32 "
        "{%0,%1,%2,%3},{%4,%5,%6,%7},{%8,%9},{%0,%1,%2,%3};"
        : "+f"(d[0]), "+f"(d[1]), "+f"(d[2]), "+f"(d[3])
        : "r"(a[0]), "r"(a[1]), "r"(a[2]), "r"(a[3]), "r"(b0), "r"(b1));
}

// ---------------- fused attention (tf32 tensor-core) ----------------
// CTA = (qtile of 32 queries, nb). 256 threads = 8 warps. Loops over 8 heads.
// smem: Ks [576][36] tf32 K (later overlaid by Vs [32][580] tf32 V^T),
//       Ss [32][580] f32 unnormalized exp(S - rowmax), small reduce buffers.
#define KSTR 36
#define SSTR 580
#define ATTN_FLOATS (SEQ*KSTR + 32*SSTR + 256 + 32 + 32)
#define ATTN_SMEM (ATTN_FLOATS*4)    // 158,464 B

__global__ __launch_bounds__(256, 1) void attn_mma(
    const float* __restrict__ qkv, float* __restrict__ o,
    float* __restrict__ attn_out, int layer)
{
    extern __shared__ float sm[];
    unsigned* Ks   = (unsigned*)sm;             // [576][36] tf32; Vs overlay [32][580]
    float* Ss      = sm + SEQ*KSTR;             // [32][580]
    float* pbuf    = Ss + 32*SSTR;              // [32][8]
    float* rowmax  = pbuf + 256;                // [32]
    float* rinv    = rowmax + 32;               // [32]

    const int tid  = threadIdx.x;
    const int lane = tid & 31;
    const int w    = tid >> 5;
    const int r4   = lane >> 2;
    const int c4   = lane & 3;
    const int qt   = blockIdx.x;                // 0..17
    const int nb   = blockIdx.y;                // 0..31
    const float* qbase = qkv + (long)nb*SEQ*768;
    const float SC = 0.17677669529663687f;      // 1/sqrt(32)

    const int sq  = tid >> 3;                   // Am row assignment
    const int kk0 = tid & 7;

    float am[72];
    #pragma unroll
    for (int j = 0; j < 72; j++) am[j] = 0.f;

    for (int h = 0; h < NHEAD; h++) {
        __syncthreads();                        // S0: Ks/Ss free from prev head
        // ---- P1: load K tile [576][32] as tf32 ----
        for (int t = tid; t < SEQ*8; t += 256) {
            int kr = t >> 3, cc = (t & 7)*4;
            float4 v = *(const float4*)&qbase[(long)kr*768 + 256 + h*32 + cc];
            unsigned* d = &Ks[kr*KSTR + cc];
            d[0] = f2tf(v.x); d[1] = f2tf(v.y); d[2] = f2tf(v.z); d[3] = f2tf(v.w);
        }
        __syncthreads();                        // S1

        // ---- P2: S = Q K^T (warp w owns key cols [w*72, w*72+72)) ----
        float acc[2][9][4];
        #pragma unroll
        for (int mt = 0; mt < 2; mt++)
            #pragma unroll
            for (int nt = 0; nt < 9; nt++)
                #pragma unroll
                for (int i = 0; i < 4; i++) acc[mt][nt][i] = 0.f;

        #pragma unroll
        for (int kc = 0; kc < 4; kc++) {
            unsigned a0[4], a1[4];
            {
                const float* qp = qbase + (long)(qt*32 + r4)*768 + h*32 + kc*8 + c4;
                a0[0] = f2tf(qp[0]*SC);        a0[2] = f2tf(qp[4]*SC);
                a0[1] = f2tf(qp[8*768]*SC);    a0[3] = f2tf(qp[8*768+4]*SC);
                const float* qp1 = qp + 16*768;
                a1[0] = f2tf(qp1[0]*SC);       a1[2] = f2tf(qp1[4]*SC);
                a1[1] = f2tf(qp1[8*768]*SC);   a1[3] = f2tf(qp1[8*768+4]*SC);
            }
            const unsigned* kb = &Ks[(w*72 + r4)*KSTR + kc*8 + c4];
            #pragma unroll
            for (int nt = 0; nt < 9; nt++) {
                unsigned b0 = kb[nt*8*KSTR], b1 = kb[nt*8*KSTR + 4];
                mma_tf32(acc[0][nt], a0, b0, b1);
                mma_tf32(acc[1][nt], a1, b0, b1);
            }
        }
        // partial row max (slots: row = s*8 + r4)
        {
            float pm[4] = {-1e30f, -1e30f, -1e30f, -1e30f};
            #pragma unroll
            for (int mt = 0; mt < 2; mt++)
                #pragma unroll
                for (int nt = 0; nt < 9; nt++) {
                    pm[mt*2+0] = fmaxf(pm[mt*2+0], fmaxf(acc[mt][nt][0], acc[mt][nt][1]));
                    pm[mt*2+1] = fmaxf(pm[mt*2+1], fmaxf(acc[mt][nt][2], acc[mt][nt][3]));
                }
            #pragma unroll
            for (int s = 0; s < 4; s++) {
                pm[s] = fmaxf(pm[s], __shfl_xor_sync(0xffffffffu, pm[s], 1));
                pm[s] = fmaxf(pm[s], __shfl_xor_sync(0xffffffffu, pm[s], 2));
            }
            if (c4 == 0) {
                #pragma unroll
                for (int s = 0; s < 4; s++) pbuf[(s*8 + r4)*8 + w] = pm[s];
            }
        }
        __syncthreads();                        // S2
        // ---- P3: rowmax reduce + load V^T (overwrites K region) ----
        if (tid < 32) {
            float m = pbuf[tid*8];
            #pragma unroll
            for (int i = 1; i < 8; i++) m = fmaxf(m, pbuf[tid*8 + i]);
            rowmax[tid] = m;
        }
        {
            unsigned* Vs = Ks;                  // [32][580] tf32 V^T
            int dh = lane, kb = w;
            #pragma unroll 2
            for (int it = 0; it < 18; it++) {
                int key4 = (kb + it*8)*4;
                const float* vp = qbase + (long)key4*768 + 512 + h*32 + dh;
                unsigned v0 = f2tf(vp[0]);
                unsigned v1 = f2tf(vp[768]);
                unsigned v2 = f2tf(vp[2*768]);
                unsigned v3 = f2tf(vp[3*768]);
                uint4 pk; pk.x = v0; pk.y = v1; pk.z = v2; pk.w = v3;
                *(uint4*)&Vs[dh*SSTR + key4] = pk;
            }
        }
        __syncthreads();                        // S3
        // ---- P4: e = exp(s - rowmax) from registers -> Ss; partial sums ----
        {
            float rm[4] = {rowmax[r4], rowmax[r4+8], rowmax[r4+16], rowmax[r4+24]};
            float ps[4] = {0.f, 0.f, 0.f, 0.f};
            #pragma unroll
            for (int mt = 0; mt < 2; mt++) {
                float* row0 = &Ss[(mt*16 + r4)*SSTR + w*72 + c4*2];
                float* row1 = row0 + 8*SSTR;
                #pragma unroll
                for (int nt = 0; nt < 9; nt++) {
                    float e0 = __expf(acc[mt][nt][0] - rm[mt*2]);
                    float e1 = __expf(acc[mt][nt][1] - rm[mt*2]);
                    float e2 = __expf(acc[mt][nt][2] - rm[mt*2+1]);
                    float e3 = __expf(acc[mt][nt][3] - rm[mt*2+1]);
                    ps[mt*2]   += e0 + e1;
                    ps[mt*2+1] += e2 + e3;
                    *(float2*)&row0[nt*8] = make_float2(e0, e1);
                    *(float2*)&row1[nt*8] = make_float2(e2, e3);
                }
            }
            #pragma unroll
            for (int s = 0; s < 4; s++) {
                ps[s] += __shfl_xor_sync(0xffffffffu, ps[s], 1);
                ps[s] += __shfl_xor_sync(0xffffffffu, ps[s], 2);
            }
            if (c4 == 0) {
                #pragma unroll
                for (int s = 0; s < 4; s++) pbuf[(s*8 + r4)*8 + w] = ps[s];
            }
        }
        __syncthreads();                        // S4
        if (tid < 32) {
            float s = 0.f;
            #pragma unroll
            for (int i = 0; i < 8; i++) s += pbuf[tid*8 + i];
            rinv[tid] = __frcp_rn(s);
        }
        __syncthreads();                        // S5
        // ---- P6: O = (E V) * rinv ; Am += E * rinv / 8 ----
        {
            const int mt = w >> 2, nt = w & 3;  // warp owns 16x8 of O
            float dv[4] = {0.f, 0.f, 0.f, 0.f};
            const unsigned* Vs = Ks;
            const float* e0b = &Ss[(mt*16 + r4)*SSTR + c4];
            const float* e1b = e0b + 8*SSTR;
            const unsigned* vb = &Vs[(nt*8 + r4)*SSTR + c4];
            #pragma unroll 8
            for (int kc = 0; kc < 72; kc++) {
                unsigned a[4];
                a[0] = f2tf(e0b[kc*8]);     a[2] = f2tf(e0b[kc*8 + 4]);
                a[1] = f2tf(e1b[kc*8]);     a[3] = f2tf(e1b[kc*8 + 4]);
                mma_tf32(dv, a, vb[kc*8], vb[kc*8 + 4]);
            }
            float ri0 = rinv[mt*16 + r4], ri1 = rinv[mt*16 + r4 + 8];
            long orow = (long)(nb*SEQ + qt*32 + mt*16 + r4)*DIM + h*32 + nt*8 + c4*2;
            *(float2*)&o[orow]          = make_float2(dv[0]*ri0, dv[1]*ri0);
            *(float2*)&o[orow + 8*DIM]  = make_float2(dv[2]*ri1, dv[3]*ri1);

            float rs = rinv[sq] * 0.125f;
            const float* sr = &Ss[sq*SSTR + kk0];
            #pragma unroll
            for (int j = 0; j < 72; j++) am[j] += sr[8*j] * rs;
        }
    }
    // ---- final: write head-mean attention ----
    float* aout = attn_out + (long)(layer*NB + nb)*SEQ*SEQ + (long)qt*32*SEQ;
    #pragma unroll
    for (int j = 0; j < 72; j++) aout[(long)sq*SEQ + kk0 + 8*j] = am[j];
}

// ---------------- feature mean over sequence ----------------
__global__ void feat_k(void) {
    int ni = blockIdx.x, b = blockIdx.y, d = threadIdx.x;
    const float* p = g_pe + ((long)(ni*BATCH + b)*SEQ)*DIM + d;
    float s = 0.f;
    for (int t = 0; t < SEQ; t++) s += p[(long)t*DIM];
    g_feat[b*(NIMG*DIM) + ni*DIM + d] = s * (1.0f/576.0f);
}

// ---------------- MLP head ----------------
__global__ void head_k(const float* __restrict__ w1, const float* __restrict__ b1,
                       const float* __restrict__ w2, const float* __restrict__ b2,
                       float* __restrict__ out) {
    __shared__ float fs[NIMG*DIM];
    __shared__ float hs[MLPDIM];
    int b = blockIdx.x, tid = threadIdx.x;
    for (int t = tid; t < NIMG*DIM; t += MLPDIM) fs[t] = g_feat[b*NIMG*DIM + t];
    __syncthreads();
    float a = b1[tid];
    const float* wr = w1 + (long)tid*(NIMG*DIM);
    for (int d2 = 0; d2 < NIMG*DIM; d2++) a += fs[d2]*wr[d2];
    hs[tid] = fmaxf(a, 0.f) * w2[tid];
    __syncthreads();
    for (int st = 256; st > 0; st >>= 1) {
        if (tid < st) hs[tid] += hs[tid + st];
        __syncthreads();
    }
    if (tid == 0) out[b] = hs[0] + b2[0];
}

// ---------------- launch ----------------
extern "C" void kernel_launch(void* const* d_in, const int* in_sizes, int n_in,
                              void* d_out, int out_size) {
    const float* x      = (const float*)d_in[0];
    const float* conv_w = (const float*)d_in[1];
    const float* conv_b = (const float*)d_in[2];
    const float* pos_e  = (const float*)d_in[3];
    const float* in_w   = (const float*)d_in[4];
    const float* in_b   = (const float*)d_in[5];
    const float* out_w  = (const float*)d_in[6];
    const float* out_b  = (const float*)d_in[7];
    const float* hw1    = (const float*)d_in[8];
    const float* hb1    = (const float*)d_in[9];
    const float* hw2    = (const float*)d_in[10];
    const float* hb2    = (const float*)d_in[11];

    float* out  = (float*)d_out;            // [8]
    float* attn = out + BATCH;              // [6,4,8,576,576]

    cudaFuncSetAttribute(attn_mma, cudaFuncAttributeMaxDynamicSharedMemorySize, ATTN_SMEM);

    float *im2col_p, *pe_p, *qkv_p, *o_p;
    cudaGetSymbolAddress((void**)&im2col_p, g_im2col);
    cudaGetSymbolAddress((void**)&pe_p,     g_pe);
    cudaGetSymbolAddress((void**)&qkv_p,    g_qkv);
    cudaGetSymbolAddress((void**)&o_p,      g_o);

    // 1) im2col
    {
        long total = (long)NIMG*BATCH*SEQ*KPATCH;
        im2col_k<<<(int)((total + 255)/256), 256>>>(x);
    }
    // 2) patch-embed GEMM per image, + conv_b + pos_enc
    {
        dim3 g(DIM/64, (BATCH*SEQ)/64, NIMG);
        sgemm64<<<g, 256>>>(im2col_p, conv_w, pe_p,
                            BATCH*SEQ, DIM, KPATCH,
                            conv_b, pos_e,
                            (long)BATCH*SEQ*KPATCH, (long)DIM*KPATCH,
                            (long)BATCH*SEQ*DIM, DIM);
    }
    // 3) transformer layers
    for (int l = 0; l < NLAYER; l++) {
        {
            dim3 g((3*DIM)/64, TOK/64, 1);
            sgemm64<<<g, 256>>>(pe_p, in_w + (long)l*3*DIM*DIM, qkv_p,
                                TOK, 3*DIM, DIM,
                                in_b + (long)l*3*DIM, nullptr, 0, 0, 0, 0);
        }
        {
            dim3 g(SEQ/32, NB, 1);
            attn_mma<<<g, 256, ATTN_SMEM>>>(qkv_p, o_p, attn, l);
        }
        {
            dim3 g(DIM/64, TOK/64, 1);
            sgemm64<<<g, 256>>>(o_p, out_w + (long)l*DIM*DIM, pe_p,
                                TOK, DIM, DIM,
                                out_b + (long)l*DIM, nullptr, 0, 0, 0, 0);
        }
    }
    // 4) sequence-mean features + MLP head
    {
        dim3 g(NIMG, BATCH);
        feat_k<<<g, DIM>>>();
    }
    head_k<<<BATCH, MLPDIM>>>(hw1, hb1, hw2, hb2, out);
}